// round 1
// baseline (speedup 1.0000x reference)
#include <cuda_runtime.h>
#include <cuda_bf16.h>
#include <cstdint>

#define NROW 4096
#define KDIM 1024
#define NTOTD 16777216.0

// ---------------- static device scratch (no allocations allowed) ----------------
static __device__ float          g_C[(size_t)NROW * NROW];      // 64 MB: raw C then standardized M
static __device__ __nv_bfloat16  g_P0[(size_t)NROW * NROW];     // 32 MB: exp(M - rowmax) in bf16
static __device__ float          g_invn[2 * NROW];              // inverse row norms (ft then fs)
static __device__ unsigned       g_rowmax_u[NROW];              // order-mapped float for atomicMax
static __device__ float          g_rowmaxM[NROW];
static __device__ float          g_u[NROW], g_v[NROW], g_T[NROW], g_af[NROW], g_Tf[NROW];
static __device__ double         g_sum, g_sumsq, g_loss;
static __device__ float          g_mean, g_invstd;
static __device__ int            g_done;

__device__ __forceinline__ unsigned fmap(float f) {
    unsigned u = __float_as_uint(f);
    return (u & 0x80000000u) ? ~u : (u | 0x80000000u);
}
__device__ __forceinline__ float funmap(unsigned s) {
    unsigned b = (s & 0x80000000u) ? (s ^ 0x80000000u) : ~s;
    return __uint_as_float(b);
}

__device__ __forceinline__ float blockReduceSum128(float v) {
    __shared__ float s[4];
    #pragma unroll
    for (int o = 16; o; o >>= 1) v += __shfl_down_sync(0xffffffffu, v, o);
    if ((threadIdx.x & 31) == 0) s[threadIdx.x >> 5] = v;
    __syncthreads();
    if (threadIdx.x == 0) v = s[0] + s[1] + s[2] + s[3];
    return v;  // valid on thread 0 only
}

// ---------------- init: reset all persistent state (graph replays!) -------------
__global__ void init_kernel() {
    int i = blockIdx.x * 256 + threadIdx.x;  // 4096 threads
    g_v[i] = 1.0f;
    g_T[i] = 0.0f;
    g_Tf[i] = 0.0f;
    g_rowmax_u[i] = 0u;
    if (i == 0) { g_done = 0; g_sum = 0.0; g_sumsq = 0.0; g_loss = 0.0; }
}

// ---------------- row norms of ft / fs ------------------------------------------
__global__ void rownorm_kernel(const float* __restrict__ ft, const float* __restrict__ fs) {
    int row = blockIdx.x;  // 0..8191
    const float* src = (row < NROW) ? ft + (size_t)row * KDIM
                                    : fs + (size_t)(row - NROW) * KDIM;
    const float4* s4 = (const float4*)src;
    float acc = 0.f;
    #pragma unroll
    for (int c = 0; c < 2; c++) {
        float4 v = s4[threadIdx.x + 128 * c];
        acc += v.x * v.x + v.y * v.y + v.z * v.z + v.w * v.w;
    }
    acc = blockReduceSum128(acc);
    if (threadIdx.x == 0) g_invn[row] = 1.0f / fmaxf(sqrtf(acc), 1e-12f);
}

// ---------------- fp32 GEMM (f32x2 packed FMA) + fused stats --------------------
// C[i][j] = dot(ft_i, fs_j) * invn_t[i] * invn_s[j]
__global__ __launch_bounds__(256, 2) void gemm_kernel(const float* __restrict__ A,
                                                      const float* __restrict__ B) {
    __shared__ float As[16][128];
    __shared__ float Bs[16][128];
    __shared__ float srmax[128][17];
    __shared__ float sred[512];

    int t = threadIdx.x;
    int tx = t & 15, ty = t >> 4;
    int bx = blockIdx.x, by = blockIdx.y;

    unsigned long long acc[8][4];
    #pragma unroll
    for (int i = 0; i < 8; i++)
        #pragma unroll
        for (int j = 0; j < 4; j++) acc[i][j] = 0ull;

    const float* Ab = A + (size_t)(by * 128) * KDIM;
    const float* Bb = B + (size_t)(bx * 128) * KDIM;

    for (int kt = 0; kt < KDIM; kt += 16) {
        #pragma unroll
        for (int s = 0; s < 2; s++) {
            int l = t + s * 256;
            int r = l >> 2, c4 = (l & 3) * 4;
            float4 a = *(const float4*)(Ab + (size_t)r * KDIM + kt + c4);
            float4 b = *(const float4*)(Bb + (size_t)r * KDIM + kt + c4);
            As[c4 + 0][r] = a.x; As[c4 + 1][r] = a.y; As[c4 + 2][r] = a.z; As[c4 + 3][r] = a.w;
            Bs[c4 + 0][r] = b.x; Bs[c4 + 1][r] = b.y; Bs[c4 + 2][r] = b.z; Bs[c4 + 3][r] = b.w;
        }
        __syncthreads();
        #pragma unroll
        for (int k = 0; k < 16; k++) {
            float4 a0 = *(const float4*)&As[k][ty * 8];
            float4 a1 = *(const float4*)&As[k][ty * 8 + 4];
            ulonglong2 blo = *(const ulonglong2*)&Bs[k][tx * 8];
            ulonglong2 bhi = *(const ulonglong2*)&Bs[k][tx * 8 + 4];
            unsigned long long bb[4] = { blo.x, blo.y, bhi.x, bhi.y };
            float av[8] = { a0.x, a0.y, a0.z, a0.w, a1.x, a1.y, a1.z, a1.w };
            #pragma unroll
            for (int i = 0; i < 8; i++) {
                unsigned long long aa;
                asm("mov.b64 %0,{%1,%1};" : "=l"(aa) : "f"(av[i]));
                #pragma unroll
                for (int j = 0; j < 4; j++)
                    asm("fma.rn.f32x2 %0,%1,%2,%0;" : "+l"(acc[i][j]) : "l"(aa), "l"(bb[j]));
            }
        }
        __syncthreads();
    }

    int row0 = by * 128 + ty * 8, col0 = bx * 128 + tx * 8;
    float ia[8], ib[8];
    #pragma unroll
    for (int i = 0; i < 8; i++) { ia[i] = g_invn[row0 + i]; ib[i] = g_invn[NROW + col0 + i]; }

    float lsum = 0.f, lsq = 0.f;
    #pragma unroll
    for (int i = 0; i < 8; i++) {
        float rmax = -3.4e38f;
        #pragma unroll
        for (int j = 0; j < 4; j++) {
            float lo, hi;
            asm("mov.b64 {%0,%1},%2;" : "=f"(lo), "=f"(hi) : "l"(acc[i][j]));
            lo *= ia[i] * ib[2 * j];
            hi *= ia[i] * ib[2 * j + 1];
            float2 st = { lo, hi };
            *(float2*)&g_C[(size_t)(row0 + i) * NROW + col0 + 2 * j] = st;
            lsum += lo + hi;
            lsq  += lo * lo + hi * hi;
            rmax = fmaxf(rmax, fmaxf(lo, hi));
        }
        srmax[ty * 8 + i][tx] = rmax;
    }

    sred[t] = lsum; sred[256 + t] = lsq;
    __syncthreads();
    for (int o = 128; o; o >>= 1) {
        if (t < o) { sred[t] += sred[t + o]; sred[256 + t] += sred[256 + t + o]; }
        __syncthreads();
    }
    if (t == 0) {
        atomicAdd(&g_sum, (double)sred[0]);
        atomicAdd(&g_sumsq, (double)sred[256]);
    }
    if (t < 128) {
        float m = -3.4e38f;
        #pragma unroll
        for (int x = 0; x < 16; x++) m = fmaxf(m, srmax[t][x]);
        atomicMax(&g_rowmax_u[by * 128 + t], fmap(m));
    }
}

// ---------------- stats: mean / invstd (ddof=1) ---------------------------------
__global__ void stats_kernel() {
    double n = NTOTD;
    double mean = g_sum / n;
    double var = (g_sumsq - g_sum * g_sum / n) / (n - 1.0);
    g_mean = (float)mean;
    g_invstd = (float)(1.0 / sqrt(var));
}

__global__ void rowmaxM_kernel() {
    int i = blockIdx.x * 256 + threadIdx.x;
    g_rowmaxM[i] = (funmap(g_rowmax_u[i]) - g_mean) * g_invstd;
}

// ---------------- standardize M (write output M) + build bf16 P0 ----------------
__global__ void transform_kernel(float* __restrict__ outM) {
    unsigned idx = blockIdx.x * 256 + threadIdx.x;  // float4 index, 4194304 total
    unsigned row = idx >> 10;
    float4 c = ((const float4*)g_C)[idx];
    float mean = g_mean, is = g_invstd, rm = g_rowmaxM[row];
    float m0 = (c.x - mean) * is;
    float m1 = (c.y - mean) * is;
    float m2 = (c.z - mean) * is;
    float m3 = (c.w - mean) * is;
    float4 mm = { m0, m1, m2, m3 };
    ((float4*)g_C)[idx] = mm;
    unsigned o = idx * 4;
    outM[o + 0] = m0; outM[o + 1] = m1; outM[o + 2] = m2; outM[o + 3] = m3;
    __nv_bfloat162 h0, h1;
    h0.x = __float2bfloat16_rn(expf(m0 - rm));
    h0.y = __float2bfloat16_rn(expf(m1 - rm));
    h1.x = __float2bfloat16_rn(expf(m2 - rm));
    h1.y = __float2bfloat16_rn(expf(m3 - rm));
    ((__nv_bfloat162*)g_P0)[idx * 2]     = h0;
    ((__nv_bfloat162*)g_P0)[idx * 2 + 1] = h1;
}

// ---------------- Sinkhorn iteration kernels ------------------------------------
#define RC_CONST 2.44140625e-4f  /* 1/4096 */

__global__ void sinkA_kernel() {  // S_i = sum_j P0[i][j]*v[j];  u_i = r/S_i
    if (g_done) return;
    int row = blockIdx.x;
    const uint4* p = (const uint4*)(g_P0 + (size_t)row * NROW);
    const float4* v4 = (const float4*)g_v;
    float acc = 0.f;
    #pragma unroll
    for (int c = 0; c < 4; c++) {
        int idx = threadIdx.x + 128 * c;
        uint4 q = p[idx];
        float4 va = v4[idx * 2], vb = v4[idx * 2 + 1];
        float2 f0 = __bfloat1622float2(*reinterpret_cast<__nv_bfloat162*>(&q.x));
        float2 f1 = __bfloat1622float2(*reinterpret_cast<__nv_bfloat162*>(&q.y));
        float2 f2 = __bfloat1622float2(*reinterpret_cast<__nv_bfloat162*>(&q.z));
        float2 f3 = __bfloat1622float2(*reinterpret_cast<__nv_bfloat162*>(&q.w));
        acc += f0.x * va.x + f0.y * va.y + f1.x * va.z + f1.y * va.w;
        acc += f2.x * vb.x + f2.y * vb.y + f3.x * vb.z + f3.y * vb.w;
    }
    acc = blockReduceSum128(acc);
    if (threadIdx.x == 0) g_u[row] = RC_CONST / acc;
}

__global__ void sinkB_kernel() {  // T_j += sum_{i in chunk} P0[i][j]*u[i]
    if (g_done) return;
    int col = blockIdx.x * 256 + threadIdx.x;
    int i0 = blockIdx.y * 128;
    const __nv_bfloat16* p = g_P0 + (size_t)i0 * NROW + col;
    float acc = 0.f;
    #pragma unroll 4
    for (int i = 0; i < 128; i++)
        acc += __bfloat162float(p[(size_t)i * NROW]) * g_u[i0 + i];
    atomicAdd(&g_T[col], acc);
}

__global__ void sinkD_kernel() {  // convergence check + v update + zero T
    __shared__ float smax[32];
    __shared__ int sflag;
    if (g_done) return;
    int t = threadIdx.x;
    float dev = 0.f;
    #pragma unroll
    for (int q = 0; q < 4; q++) {
        int j = t + 1024 * q;
        dev = fmaxf(dev, fabsf(g_v[j] * g_T[j] - RC_CONST));
    }
    #pragma unroll
    for (int o = 16; o; o >>= 1) dev = fmaxf(dev, __shfl_down_sync(0xffffffffu, dev, o));
    if ((t & 31) == 0) smax[t >> 5] = dev;
    __syncthreads();
    if (t == 0) {
        float m = 0.f;
        #pragma unroll
        for (int w = 0; w < 32; w++) m = fmaxf(m, smax[w]);
        sflag = (m <= 1e-6f) ? 1 : 0;
        if (sflag) g_done = 1;
    }
    __syncthreads();
    if (!sflag) {
        #pragma unroll
        for (int q = 0; q < 4; q++) {
            int j = t + 1024 * q;
            g_v[j] = RC_CONST / g_T[j];
        }
    }
    #pragma unroll
    for (int q = 0; q < 4; q++) g_T[t + 1024 * q] = 0.f;
}

// ---------------- final renormalization (fp32 P0 recomputed from M) -------------
__global__ void f1_kernel() {  // af_i = 1 / sum_j exp(M_ij - rmax_i)*v_j
    int row = blockIdx.x;
    const float4* m4 = (const float4*)(g_C + (size_t)row * NROW);
    const float4* v4 = (const float4*)g_v;
    float rm = g_rowmaxM[row], acc = 0.f;
    #pragma unroll
    for (int c = 0; c < 8; c++) {
        int idx = threadIdx.x + 128 * c;
        float4 m = m4[idx];
        float4 v = v4[idx];
        acc += expf(m.x - rm) * v.x + expf(m.y - rm) * v.y
             + expf(m.z - rm) * v.z + expf(m.w - rm) * v.w;
    }
    acc = blockReduceSum128(acc);
    if (threadIdx.x == 0) g_af[row] = 1.0f / acc;
}

__global__ void f2_kernel() {  // Tf_j += sum_i exp(M_ij - rmax_i)*af_i
    int col = blockIdx.x * 256 + threadIdx.x;
    int i0 = blockIdx.y * 128;
    const float* p = g_C + (size_t)i0 * NROW + col;
    float acc = 0.f;
    #pragma unroll 4
    for (int i = 0; i < 128; i++)
        acc += expf(p[(size_t)i * NROW] - g_rowmaxM[i0 + i]) * g_af[i0 + i];
    atomicAdd(&g_Tf[col], acc);
}

__global__ void f2b_kernel() {  // invert Tf
    int i = blockIdx.x * 256 + threadIdx.x;
    g_Tf[i] = 1.0f / g_Tf[i];
}

__global__ void f3_kernel(float* __restrict__ outP) {  // P + loss accumulation
    int row = blockIdx.x;
    float rm = g_rowmaxM[row], a = g_af[row];
    const float4* m4 = (const float4*)(g_C + (size_t)row * NROW);
    float* op = outP + (size_t)row * NROW;
    float lacc = 0.f;
    #pragma unroll
    for (int c = 0; c < 8; c++) {
        int idx = threadIdx.x + 128 * c;
        float4 m = m4[idx];
        int j0 = idx * 4;
        float p0 = expf(m.x - rm) * a * g_Tf[j0 + 0];
        float p1 = expf(m.y - rm) * a * g_Tf[j0 + 1];
        float p2 = expf(m.z - rm) * a * g_Tf[j0 + 2];
        float p3 = expf(m.w - rm) * a * g_Tf[j0 + 3];
        op[j0 + 0] = p0; op[j0 + 1] = p1; op[j0 + 2] = p2; op[j0 + 3] = p3;
        float d0 = p0 - ((j0 + 0) == row ? 1.0f : 0.0f);
        float d1 = p1 - ((j0 + 1) == row ? 1.0f : 0.0f);
        float d2 = p2 - ((j0 + 2) == row ? 1.0f : 0.0f);
        float d3 = p3 - ((j0 + 3) == row ? 1.0f : 0.0f);
        lacc += d0 * d0 + d1 * d1 + d2 * d2 + d3 * d3;
    }
    lacc = blockReduceSum128(lacc);
    if (threadIdx.x == 0) atomicAdd(&g_loss, (double)lacc);
}

__global__ void f4_kernel(float* __restrict__ out) {
    out[0] = (float)sqrt(g_loss);
}

// ---------------- launch --------------------------------------------------------
extern "C" void kernel_launch(void* const* d_in, const int* in_sizes, int n_in,
                              void* d_out, int out_size) {
    const float* ft = (const float*)d_in[0];
    const float* fs = (const float*)d_in[1];
    float* out = (float*)d_out;
    float* outP = out + 1;
    float* outM = out + 1 + (size_t)NROW * NROW;

    init_kernel<<<16, 256>>>();
    rownorm_kernel<<<2 * NROW, 128>>>(ft, fs);
    gemm_kernel<<<dim3(32, 32), 256>>>(ft, fs);
    stats_kernel<<<1, 1>>>();
    rowmaxM_kernel<<<16, 256>>>();
    transform_kernel<<<16384, 256>>>(outM);

    for (int it = 0; it < 20; ++it) {
        sinkA_kernel<<<NROW, 128>>>();
        sinkB_kernel<<<dim3(16, 32), 256>>>();
        sinkD_kernel<<<1, 1024>>>();
    }

    f1_kernel<<<NROW, 128>>>();
    f2_kernel<<<dim3(16, 32), 256>>>();
    f2b_kernel<<<16, 256>>>();
    f3_kernel<<<NROW, 128>>>(outP);
    f4_kernel<<<1, 1>>>(out);
}

// round 6
// speedup vs baseline: 1.8780x; 1.8780x over previous
#include <cuda_runtime.h>
#include <cuda_bf16.h>
#include <cstdint>

#define NROW 4096
#define KDIM 1024
#define NTOTD 16777216.0

// ---------------- static device scratch (no allocations allowed) ----------------
static __device__ float          g_C[(size_t)NROW * NROW];      // 64 MB: raw C then standardized M
static __device__ __nv_bfloat16  g_P0[(size_t)NROW * NROW];     // 32 MB: exp(M - rowmax) in bf16
static __device__ __nv_bfloat16  g_Ah[(size_t)NROW * KDIM];     // prescaled ft hi
static __device__ __nv_bfloat16  g_Al[(size_t)NROW * KDIM];     // prescaled ft lo
static __device__ __nv_bfloat16  g_Bh[(size_t)NROW * KDIM];     // prescaled fs hi
static __device__ __nv_bfloat16  g_Bl[(size_t)NROW * KDIM];     // prescaled fs lo
static __device__ float          g_invn[2 * NROW];              // inverse row norms (ft then fs)
static __device__ unsigned       g_rowmax_u[NROW];              // order-mapped float for atomicMax
static __device__ float          g_rowmaxM[NROW];
static __device__ float          g_u[NROW], g_v[NROW], g_T[NROW], g_af[NROW], g_Tf[NROW];
static __device__ double         g_sum, g_sumsq, g_loss;
static __device__ float          g_mean, g_invstd;
static __device__ int            g_done;
static __device__ unsigned       g_ctr;                         // last-block ticket counter

__device__ __forceinline__ unsigned fmap(float f) {
    unsigned u = __float_as_uint(f);
    return (u & 0x80000000u) ? ~u : (u | 0x80000000u);
}
__device__ __forceinline__ float funmap(unsigned s) {
    unsigned b = (s & 0x80000000u) ? (s ^ 0x80000000u) : ~s;
    return __uint_as_float(b);
}

__device__ __forceinline__ float blockReduceSum128(float v) {
    __shared__ float s[4];
    #pragma unroll
    for (int o = 16; o; o >>= 1) v += __shfl_down_sync(0xffffffffu, v, o);
    if ((threadIdx.x & 31) == 0) s[threadIdx.x >> 5] = v;
    __syncthreads();
    if (threadIdx.x == 0) v = s[0] + s[1] + s[2] + s[3];
    return v;  // valid on thread 0 only
}

// ---------------- init: reset all persistent state (graph replays!) -------------
__global__ void init_kernel() {
    int i = blockIdx.x * 256 + threadIdx.x;  // 4096 threads
    g_v[i] = 1.0f;
    g_T[i] = 0.0f;
    g_Tf[i] = 0.0f;
    g_rowmax_u[i] = 0u;
    if (i == 0) { g_done = 0; g_sum = 0.0; g_sumsq = 0.0; g_loss = 0.0; g_ctr = 0u; }
}

// ---------------- row norms of ft / fs ------------------------------------------
__global__ void rownorm_kernel(const float* __restrict__ ft, const float* __restrict__ fs) {
    int row = blockIdx.x;  // 0..8191
    const float* src = (row < NROW) ? ft + (size_t)row * KDIM
                                    : fs + (size_t)(row - NROW) * KDIM;
    const float4* s4 = (const float4*)src;
    float acc = 0.f;
    #pragma unroll
    for (int c = 0; c < 2; c++) {
        float4 v = s4[threadIdx.x + 128 * c];
        acc += v.x * v.x + v.y * v.y + v.z * v.z + v.w * v.w;
    }
    acc = blockReduceSum128(acc);
    if (threadIdx.x == 0) g_invn[row] = 1.0f / fmaxf(sqrtf(acc), 1e-12f);
}

// ---------------- split: prescale by invn, hi/lo bf16 decomposition -------------
__global__ void split_kernel(const float* __restrict__ ft, const float* __restrict__ fs) {
    int i = blockIdx.x * 256 + threadIdx.x;   // float4 index, 2*4096*256 total
    int row = i >> 8;                         // 0..8191
    float sc = g_invn[row];
    float4 v;
    if (row < NROW) v = ((const float4*)ft)[i];
    else            v = ((const float4*)fs)[i - NROW * 256];
    v.x *= sc; v.y *= sc; v.z *= sc; v.w *= sc;
    __nv_bfloat16 h0 = __float2bfloat16_rn(v.x);
    __nv_bfloat16 h1 = __float2bfloat16_rn(v.y);
    __nv_bfloat16 h2 = __float2bfloat16_rn(v.z);
    __nv_bfloat16 h3 = __float2bfloat16_rn(v.w);
    __nv_bfloat16 l0 = __float2bfloat16_rn(v.x - __bfloat162float(h0));
    __nv_bfloat16 l1 = __float2bfloat16_rn(v.y - __bfloat162float(h1));
    __nv_bfloat16 l2 = __float2bfloat16_rn(v.z - __bfloat162float(h2));
    __nv_bfloat16 l3 = __float2bfloat16_rn(v.w - __bfloat162float(h3));
    __nv_bfloat162 hp0 = { h0, h1 }, hp1 = { h2, h3 };
    __nv_bfloat162 lp0 = { l0, l1 }, lp1 = { l2, l3 };
    if (row < NROW) {
        ((__nv_bfloat162*)g_Ah)[i * 2] = hp0; ((__nv_bfloat162*)g_Ah)[i * 2 + 1] = hp1;
        ((__nv_bfloat162*)g_Al)[i * 2] = lp0; ((__nv_bfloat162*)g_Al)[i * 2 + 1] = lp1;
    } else {
        int j = i - NROW * 256;
        ((__nv_bfloat162*)g_Bh)[j * 2] = hp0; ((__nv_bfloat162*)g_Bh)[j * 2 + 1] = hp1;
        ((__nv_bfloat162*)g_Bl)[j * 2] = lp0; ((__nv_bfloat162*)g_Bl)[j * 2 + 1] = lp1;
    }
}

// ---------------- mma.sync bf16 hi/lo GEMM + fused stats ------------------------
// C[i][j] = Ah_i.Bh_j + Ah_i.Bl_j + Al_i.Bh_j  (fp32 accumulate in registers)
// CTA tile 128x128, 8 warps (2 M x 4 N), warp tile 64x32, BK=32, cp.async dbl-buf.
#define RSB   80u        /* smem bytes per 32-element bf16 row (64B data + 16B pad) */
#define MATSZ 10240u     /* 128 rows * RSB */
#define STAGE (4u * MATSZ)
#define GEMM_SMEM (2 * 4 * 10240)

__device__ __forceinline__ uint32_t s2u(const void* p) {
    uint32_t a;
    asm("{ .reg .u64 t; cvta.to.shared.u64 t, %1; cvt.u32.u64 %0, t; }" : "=r"(a) : "l"(p));
    return a;
}

#define LDSM4(R, addr)                                                              \
    asm volatile("ldmatrix.sync.aligned.m8n8.x4.shared.b16 {%0,%1,%2,%3}, [%4];"    \
                 : "=r"((R)[0]), "=r"((R)[1]), "=r"((R)[2]), "=r"((R)[3])           \
                 : "r"(addr))

__device__ __forceinline__ void mma16816(float* d, const uint32_t* a, const uint32_t* b) {
    asm volatile(
        "mma.sync.aligned.m16n8k16.row.col.f32.bf16.bf16.f32 "
        "{%0,%1,%2,%3}, {%4,%5,%6,%7}, {%8,%9}, {%0,%1,%2,%3};"
        : "+f"(d[0]), "+f"(d[1]), "+f"(d[2]), "+f"(d[3])
        : "r"(a[0]), "r"(a[1]), "r"(a[2]), "r"(a[3]), "r"(b[0]), "r"(b[1]));
}

__global__ __launch_bounds__(256, 1) void gemm_mma_kernel() {
    extern __shared__ char smem[];
    uint32_t sb = s2u(smem);
    int t = threadIdx.x, lane = t & 31, wid = t >> 5;
    int bx = blockIdx.x, by = blockIdx.y;
    int warpM = wid >> 2, warpN = wid & 3;

    const char* gb[4] = {
        (const char*)(g_Ah + (size_t)(by * 128) * KDIM),
        (const char*)(g_Al + (size_t)(by * 128) * KDIM),
        (const char*)(g_Bh + (size_t)(bx * 128) * KDIM),
        (const char*)(g_Bl + (size_t)(bx * 128) * KDIM)
    };

    // per-thread load slots: 2048 16B transfers per stage / 256 threads = 8
    int mats[8], lr[8], lo[8];
    #pragma unroll
    for (int i = 0; i < 8; i++) {
        int idx = i * 256 + t;
        mats[i] = idx >> 9;
        int rem = idx & 511;
        lr[i] = rem >> 2;
        lo[i] = rem & 3;
    }

    float acc[4][4][4];
    #pragma unroll
    for (int a = 0; a < 4; a++)
        #pragma unroll
        for (int b = 0; b < 4; b++)
            #pragma unroll
            for (int c = 0; c < 4; c++) acc[a][b][c] = 0.f;

    const uint32_t aoff = (uint32_t)(warpM * 64 + (lane & 15)) * RSB;
    const uint32_t boff = (uint32_t)(warpN * 32 + (lane & 15)) * RSB;
    const uint32_t khalf = (lane & 16) ? 16u : 0u;  // byte offset of k-half

    // ---- issue stage 0 ----
    #pragma unroll
    for (int i = 0; i < 8; i++) {
        const char* g = gb[mats[i]] + (size_t)lr[i] * 2048 + lo[i] * 16;
        uint32_t s = sb + mats[i] * MATSZ + lr[i] * RSB + lo[i] * 16;
        asm volatile("cp.async.cg.shared.global [%0], [%1], 16;" :: "r"(s), "l"(g));
    }
    asm volatile("cp.async.commit_group;" ::: "memory");

    for (int c = 0; c < 32; c++) {
        if (c < 31) {
            uint32_t bs = sb + ((c + 1) & 1) * STAGE;
            int ko = (c + 1) * 64;
            #pragma unroll
            for (int i = 0; i < 8; i++) {
                const char* g = gb[mats[i]] + (size_t)lr[i] * 2048 + ko + lo[i] * 16;
                uint32_t s = bs + mats[i] * MATSZ + lr[i] * RSB + lo[i] * 16;
                asm volatile("cp.async.cg.shared.global [%0], [%1], 16;" :: "r"(s), "l"(g));
            }
            asm volatile("cp.async.commit_group;" ::: "memory");
            asm volatile("cp.async.wait_group 1;" ::: "memory");
        } else {
            asm volatile("cp.async.wait_group 0;" ::: "memory");
        }
        __syncthreads();

        uint32_t base = sb + (c & 1) * STAGE;
        #pragma unroll
        for (int kc = 0; kc < 2; kc++) {
            uint32_t kb = kc * 32 + khalf;
            uint32_t ah[4][4], al[4][4], bh[4][2], bl[4][2];
            #pragma unroll
            for (int mt = 0; mt < 4; mt++) {
                LDSM4(ah[mt], base + 0 * MATSZ + aoff + mt * 16 * RSB + kb);
                LDSM4(al[mt], base + 1 * MATSZ + aoff + mt * 16 * RSB + kb);
            }
            #pragma unroll
            for (int np = 0; np < 2; np++) {
                uint32_t r[4];
                LDSM4(r, base + 2 * MATSZ + boff + np * 16 * RSB + kb);
                bh[np * 2][0] = r[0]; bh[np * 2][1] = r[2];
                bh[np * 2 + 1][0] = r[1]; bh[np * 2 + 1][1] = r[3];
                LDSM4(r, base + 3 * MATSZ + boff + np * 16 * RSB + kb);
                bl[np * 2][0] = r[0]; bl[np * 2][1] = r[2];
                bl[np * 2 + 1][0] = r[1]; bl[np * 2 + 1][1] = r[3];
            }
            #pragma unroll
            for (int mt = 0; mt < 4; mt++)
                #pragma unroll
                for (int nt = 0; nt < 4; nt++) {
                    mma16816(acc[mt][nt], ah[mt], bh[nt]);
                    mma16816(acc[mt][nt], ah[mt], bl[nt]);
                    mma16816(acc[mt][nt], al[mt], bh[nt]);
                }
        }
        __syncthreads();
    }

    // ---- epilogue: write C + fused stats ----
    unsigned* smax = (unsigned*)smem;           // 128 entries
    float* sred = (float*)(smem + 512);
    if (t < 128) smax[t] = 0u;
    __syncthreads();

    float lsum = 0.f, lsq = 0.f;
    int q = lane >> 2, pr = (lane & 3) * 2;
    #pragma unroll
    for (int mt = 0; mt < 4; mt++) {
        float rm0 = -3.4e38f, rm1 = -3.4e38f;
        int lrow0 = warpM * 64 + mt * 16 + q;
        int gr0 = by * 128 + lrow0;
        #pragma unroll
        for (int nt = 0; nt < 4; nt++) {
            float c0 = acc[mt][nt][0], c1 = acc[mt][nt][1];
            float c2 = acc[mt][nt][2], c3 = acc[mt][nt][3];
            int col = bx * 128 + warpN * 32 + nt * 8 + pr;
            float2 w0 = { c0, c1 }, w1 = { c2, c3 };
            *(float2*)&g_C[(size_t)gr0 * NROW + col] = w0;
            *(float2*)&g_C[(size_t)(gr0 + 8) * NROW + col] = w1;
            lsum += (c0 + c1) + (c2 + c3);
            lsq += c0 * c0 + c1 * c1 + c2 * c2 + c3 * c3;
            rm0 = fmaxf(rm0, fmaxf(c0, c1));
            rm1 = fmaxf(rm1, fmaxf(c2, c3));
        }
        atomicMax(&smax[lrow0], fmap(rm0));
        atomicMax(&smax[lrow0 + 8], fmap(rm1));
    }

    #pragma unroll
    for (int o = 16; o; o >>= 1) {
        lsum += __shfl_down_sync(0xffffffffu, lsum, o);
        lsq  += __shfl_down_sync(0xffffffffu, lsq,  o);
    }
    if (lane == 0) { sred[wid] = lsum; sred[8 + wid] = lsq; }
    __syncthreads();
    if (t == 0) {
        float s0 = 0.f, s1 = 0.f;
        #pragma unroll
        for (int w = 0; w < 8; w++) { s0 += sred[w]; s1 += sred[8 + w]; }
        atomicAdd(&g_sum, (double)s0);
        atomicAdd(&g_sumsq, (double)s1);
    }
    if (t < 128) atomicMax(&g_rowmax_u[by * 128 + t], smax[t]);
}

// ---------------- stats: mean / invstd (ddof=1) ---------------------------------
__global__ void stats_kernel() {
    double n = NTOTD;
    double mean = g_sum / n;
    double var = (g_sumsq - g_sum * g_sum / n) / (n - 1.0);
    g_mean = (float)mean;
    g_invstd = (float)(1.0 / sqrt(var));
}

__global__ void rowmaxM_kernel() {
    int i = blockIdx.x * 256 + threadIdx.x;
    g_rowmaxM[i] = (funmap(g_rowmax_u[i]) - g_mean) * g_invstd;
}

// ---------------- standardize M (write output M) + build bf16 P0 ----------------
__global__ void transform_kernel(float* __restrict__ outM) {
    unsigned idx = blockIdx.x * 256 + threadIdx.x;  // float4 index, 4194304 total
    unsigned row = idx >> 10;
    float4 c = ((const float4*)g_C)[idx];
    float mean = g_mean, is = g_invstd, rm = g_rowmaxM[row];
    float m0 = (c.x - mean) * is;
    float m1 = (c.y - mean) * is;
    float m2 = (c.z - mean) * is;
    float m3 = (c.w - mean) * is;
    float4 mm = { m0, m1, m2, m3 };
    ((float4*)g_C)[idx] = mm;
    unsigned o = idx * 4;
    outM[o + 0] = m0; outM[o + 1] = m1; outM[o + 2] = m2; outM[o + 3] = m3;
    __nv_bfloat162 h0, h1;
    h0.x = __float2bfloat16_rn(expf(m0 - rm));
    h0.y = __float2bfloat16_rn(expf(m1 - rm));
    h1.x = __float2bfloat16_rn(expf(m2 - rm));
    h1.y = __float2bfloat16_rn(expf(m3 - rm));
    ((__nv_bfloat162*)g_P0)[idx * 2]     = h0;
    ((__nv_bfloat162*)g_P0)[idx * 2 + 1] = h1;
}

// ---------------- Sinkhorn iteration kernels ------------------------------------
#define RC_CONST 2.44140625e-4f  /* 1/4096 */

__global__ void sinkA_kernel() {  // S_i = sum_j P0[i][j]*v[j];  u_i = r/S_i
    if (g_done) return;
    int row = blockIdx.x;
    const uint4* p = (const uint4*)(g_P0 + (size_t)row * NROW);
    const float4* v4 = (const float4*)g_v;
    float acc = 0.f;
    #pragma unroll
    for (int c = 0; c < 4; c++) {
        int idx = threadIdx.x + 128 * c;
        uint4 q = p[idx];
        float4 va = v4[idx * 2], vb = v4[idx * 2 + 1];
        float2 f0 = __bfloat1622float2(*reinterpret_cast<__nv_bfloat162*>(&q.x));
        float2 f1 = __bfloat1622float2(*reinterpret_cast<__nv_bfloat162*>(&q.y));
        float2 f2 = __bfloat1622float2(*reinterpret_cast<__nv_bfloat162*>(&q.z));
        float2 f3 = __bfloat1622float2(*reinterpret_cast<__nv_bfloat162*>(&q.w));
        acc += f0.x * va.x + f0.y * va.y + f1.x * va.z + f1.y * va.w;
        acc += f2.x * vb.x + f2.y * vb.y + f3.x * vb.z + f3.y * vb.w;
    }
    acc = blockReduceSum128(acc);
    if (threadIdx.x == 0) g_u[row] = RC_CONST / acc;
}

// sinkB: column pass + last-block-done finalize (absorbs old sinkD kernel)
__global__ void sinkB_kernel() {
    __shared__ unsigned ticket;
    __shared__ float smax[8];
    __shared__ int sflag;
    if (g_done) return;
    int t = threadIdx.x;
    int col = blockIdx.x * 256 + t;
    int i0 = blockIdx.y * 128;
    const __nv_bfloat16* p = g_P0 + (size_t)i0 * NROW + col;
    float acc = 0.f;
    #pragma unroll 4
    for (int i = 0; i < 128; i++)
        acc += __bfloat162float(p[(size_t)i * NROW]) * g_u[i0 + i];
    atomicAdd(&g_T[col], acc);
    __threadfence();
    if (t == 0) ticket = atomicAdd(&g_ctr, 1u);
    __syncthreads();
    if (ticket != 511u) return;   // not the last block

    // ---- finalize (runs in exactly one block, after all T contributions) ----
    float tv[16], dev = 0.f;
    #pragma unroll
    for (int q = 0; q < 16; q++) {
        int j = t + 256 * q;
        tv[q] = g_T[j];
        dev = fmaxf(dev, fabsf(g_v[j] * tv[q] - RC_CONST));
    }
    #pragma unroll
    for (int o = 16; o; o >>= 1) dev = fmaxf(dev, __shfl_down_sync(0xffffffffu, dev, o));
    if ((t & 31) == 0) smax[t >> 5] = dev;
    __syncthreads();
    if (t == 0) {
        float m = 0.f;
        #pragma unroll
        for (int w = 0; w < 8; w++) m = fmaxf(m, smax[w]);
        sflag = (m <= 1e-6f) ? 1 : 0;
        if (sflag) g_done = 1;
        g_ctr = 0u;               // reset ticket for next iteration / replay
    }
    __syncthreads();
    #pragma unroll
    for (int q = 0; q < 16; q++) {
        int j = t + 256 * q;
        if (!sflag) g_v[j] = RC_CONST / tv[q];
        g_T[j] = 0.f;
    }
}

// ---------------- final renormalization (fp32 P0 recomputed from M) -------------
__global__ void f1_kernel() {  // af_i = 1 / sum_j exp(M_ij - rmax_i)*v_j
    int row = blockIdx.x;
    const float4* m4 = (const float4*)(g_C + (size_t)row * NROW);
    const float4* v4 = (const float4*)g_v;
    float rm = g_rowmaxM[row], acc = 0.f;
    #pragma unroll
    for (int c = 0; c < 8; c++) {
        int idx = threadIdx.x + 128 * c;
        float4 m = m4[idx];
        float4 v = v4[idx];
        acc += expf(m.x - rm) * v.x + expf(m.y - rm) * v.y
             + expf(m.z - rm) * v.z + expf(m.w - rm) * v.w;
    }
    acc = blockReduceSum128(acc);
    if (threadIdx.x == 0) g_af[row] = 1.0f / acc;
}

// f2: column pass + last-block inversion of Tf (absorbs old f2b kernel)
__global__ void f2_kernel() {
    __shared__ unsigned ticket;
    int t = threadIdx.x;
    int col = blockIdx.x * 256 + t;
    int i0 = blockIdx.y * 128;
    const float* p = g_C + (size_t)i0 * NROW + col;
    float acc = 0.f;
    #pragma unroll 4
    for (int i = 0; i < 128; i++)
        acc += expf(p[(size_t)i * NROW] - g_rowmaxM[i0 + i]) * g_af[i0 + i];
    atomicAdd(&g_Tf[col], acc);
    __threadfence();
    if (t == 0) ticket = atomicAdd(&g_ctr, 1u);
    __syncthreads();
    if (ticket != 511u) return;
    #pragma unroll
    for (int q = 0; q < 16; q++) {
        int j = t + 256 * q;
        g_Tf[j] = 1.0f / g_Tf[j];
    }
    if (t == 0) g_ctr = 0u;
}

__global__ void f3_kernel(float* __restrict__ outP) {  // P + loss accumulation
    int row = blockIdx.x;
    float rm = g_rowmaxM[row], a = g_af[row];
    const float4* m4 = (const float4*)(g_C + (size_t)row * NROW);
    float* op = outP + (size_t)row * NROW;
    float lacc = 0.f;
    #pragma unroll
    for (int c = 0; c < 8; c++) {
        int idx = threadIdx.x + 128 * c;
        float4 m = m4[idx];
        int j0 = idx * 4;
        float p0 = expf(m.x - rm) * a * g_Tf[j0 + 0];
        float p1 = expf(m.y - rm) * a * g_Tf[j0 + 1];
        float p2 = expf(m.z - rm) * a * g_Tf[j0 + 2];
        float p3 = expf(m.w - rm) * a * g_Tf[j0 + 3];
        op[j0 + 0] = p0; op[j0 + 1] = p1; op[j0 + 2] = p2; op[j0 + 3] = p3;
        float d0 = p0 - ((j0 + 0) == row ? 1.0f : 0.0f);
        float d1 = p1 - ((j0 + 1) == row ? 1.0f : 0.0f);
        float d2 = p2 - ((j0 + 2) == row ? 1.0f : 0.0f);
        float d3 = p3 - ((j0 + 3) == row ? 1.0f : 0.0f);
        lacc += d0 * d0 + d1 * d1 + d2 * d2 + d3 * d3;
    }
    lacc = blockReduceSum128(lacc);
    if (threadIdx.x == 0) atomicAdd(&g_loss, (double)lacc);
}

__global__ void f4_kernel(float* __restrict__ out) {
    out[0] = (float)sqrt(g_loss);
}

// ---------------- launch --------------------------------------------------------
extern "C" void kernel_launch(void* const* d_in, const int* in_sizes, int n_in,
                              void* d_out, int out_size) {
    const float* ft = (const float*)d_in[0];
    const float* fs = (const float*)d_in[1];
    float* out = (float*)d_out;
    float* outP = out + 1;
    float* outM = out + 1 + (size_t)NROW * NROW;

    cudaFuncSetAttribute(gemm_mma_kernel, cudaFuncAttributeMaxDynamicSharedMemorySize,
                         GEMM_SMEM);

    init_kernel<<<16, 256>>>();
    rownorm_kernel<<<2 * NROW, 128>>>(ft, fs);
    split_kernel<<<8192, 256>>>(ft, fs);
    gemm_mma_kernel<<<dim3(32, 32), 256, GEMM_SMEM>>>();
    stats_kernel<<<1, 1>>>();
    rowmaxM_kernel<<<16, 256>>>();
    transform_kernel<<<16384, 256>>>(outM);

    for (int it = 0; it < 20; ++it) {
        sinkA_kernel<<<NROW, 128>>>();
        sinkB_kernel<<<dim3(16, 32), 256>>>();
    }

    f1_kernel<<<NROW, 128>>>();
    f2_kernel<<<dim3(16, 32), 256>>>();
    f3_kernel<<<NROW, 128>>>(outP);
    f4_kernel<<<1, 1>>>(out);
}

// round 14
// speedup vs baseline: 1.8847x; 1.0036x over previous
#include <cuda_runtime.h>
#include <cuda_bf16.h>
#include <cstdint>

#define NROW 4096
#define KDIM 1024
#define NTOTD 16777216.0

// ---------------- static device scratch (no allocations allowed) ----------------
static __device__ float          g_C[(size_t)NROW * NROW];      // 64 MB: raw C then standardized M
static __device__ __nv_bfloat16  g_P0[(size_t)NROW * NROW];     // 32 MB: exp(M - rowmax) in bf16
static __device__ __nv_bfloat16  g_Ah[(size_t)NROW * KDIM];     // prescaled ft hi
static __device__ __nv_bfloat16  g_Al[(size_t)NROW * KDIM];     // prescaled ft lo
static __device__ __nv_bfloat16  g_Bh[(size_t)NROW * KDIM];     // prescaled fs hi
static __device__ __nv_bfloat16  g_Bl[(size_t)NROW * KDIM];     // prescaled fs lo
static __device__ float          g_invn[2 * NROW];              // inverse row norms (ft then fs)
static __device__ unsigned       g_rowmax_u[NROW];              // order-mapped float for atomicMax
static __device__ float          g_rowmaxM[NROW];
static __device__ float          g_u[NROW], g_v[NROW], g_T[NROW], g_af[NROW], g_Tf[NROW];
static __device__ double         g_sum, g_sumsq, g_loss;
static __device__ float          g_mean, g_invstd;
static __device__ int            g_done;
static __device__ unsigned       g_ctr;                         // last-block ticket counter

__device__ __forceinline__ unsigned fmap(float f) {
    unsigned u = __float_as_uint(f);
    return (u & 0x80000000u) ? ~u : (u | 0x80000000u);
}
__device__ __forceinline__ float funmap(unsigned s) {
    unsigned b = (s & 0x80000000u) ? (s ^ 0x80000000u) : ~s;
    return __uint_as_float(b);
}

__device__ __forceinline__ float blockReduceSum128(float v) {
    __shared__ float s[4];
    #pragma unroll
    for (int o = 16; o; o >>= 1) v += __shfl_down_sync(0xffffffffu, v, o);
    if ((threadIdx.x & 31) == 0) s[threadIdx.x >> 5] = v;
    __syncthreads();
    if (threadIdx.x == 0) v = s[0] + s[1] + s[2] + s[3];
    return v;  // valid on thread 0 only
}

// ---------------- init: reset all persistent state (graph replays!) -------------
__global__ void init_kernel() {
    int i = blockIdx.x * 256 + threadIdx.x;  // 4096 threads
    g_v[i] = 1.0f;
    g_T[i] = 0.0f;
    g_Tf[i] = 0.0f;
    g_rowmax_u[i] = 0u;
    if (i == 0) { g_done = 0; g_sum = 0.0; g_sumsq = 0.0; g_loss = 0.0; g_ctr = 0u; }
}

// ---------------- row norms of ft / fs ------------------------------------------
__global__ void rownorm_kernel(const float* __restrict__ ft, const float* __restrict__ fs) {
    int row = blockIdx.x;  // 0..8191
    const float* src = (row < NROW) ? ft + (size_t)row * KDIM
                                    : fs + (size_t)(row - NROW) * KDIM;
    const float4* s4 = (const float4*)src;
    float acc = 0.f;
    #pragma unroll
    for (int c = 0; c < 2; c++) {
        float4 v = s4[threadIdx.x + 128 * c];
        acc += v.x * v.x + v.y * v.y + v.z * v.z + v.w * v.w;
    }
    acc = blockReduceSum128(acc);
    if (threadIdx.x == 0) g_invn[row] = 1.0f / fmaxf(sqrtf(acc), 1e-12f);
}

// ---------------- split: prescale by invn, hi/lo bf16 decomposition -------------
__global__ void split_kernel(const float* __restrict__ ft, const float* __restrict__ fs) {
    int i = blockIdx.x * 256 + threadIdx.x;   // float4 index, 2*4096*256 total
    int row = i >> 8;                         // 0..8191
    float sc = g_invn[row];
    float4 v;
    if (row < NROW) v = ((const float4*)ft)[i];
    else            v = ((const float4*)fs)[i - NROW * 256];
    v.x *= sc; v.y *= sc; v.z *= sc; v.w *= sc;
    __nv_bfloat16 h0 = __float2bfloat16_rn(v.x);
    __nv_bfloat16 h1 = __float2bfloat16_rn(v.y);
    __nv_bfloat16 h2 = __float2bfloat16_rn(v.z);
    __nv_bfloat16 h3 = __float2bfloat16_rn(v.w);
    __nv_bfloat16 l0 = __float2bfloat16_rn(v.x - __bfloat162float(h0));
    __nv_bfloat16 l1 = __float2bfloat16_rn(v.y - __bfloat162float(h1));
    __nv_bfloat16 l2 = __float2bfloat16_rn(v.z - __bfloat162float(h2));
    __nv_bfloat16 l3 = __float2bfloat16_rn(v.w - __bfloat162float(h3));
    __nv_bfloat162 hp0 = { h0, h1 }, hp1 = { h2, h3 };
    __nv_bfloat162 lp0 = { l0, l1 }, lp1 = { l2, l3 };
    if (row < NROW) {
        ((__nv_bfloat162*)g_Ah)[i * 2] = hp0; ((__nv_bfloat162*)g_Ah)[i * 2 + 1] = hp1;
        ((__nv_bfloat162*)g_Al)[i * 2] = lp0; ((__nv_bfloat162*)g_Al)[i * 2 + 1] = lp1;
    } else {
        int j = i - NROW * 256;
        ((__nv_bfloat162*)g_Bh)[j * 2] = hp0; ((__nv_bfloat162*)g_Bh)[j * 2 + 1] = hp1;
        ((__nv_bfloat162*)g_Bl)[j * 2] = lp0; ((__nv_bfloat162*)g_Bl)[j * 2 + 1] = lp1;
    }
}

// ---------------- mma.sync bf16 hi/lo GEMM + fused stats ------------------------
// C[i][j] = Ah_i.Bh_j + Ah_i.Bl_j + Al_i.Bh_j  (fp32 accumulate in registers)
// CTA tile 128x128, 8 warps (2 M x 4 N), warp tile 64x32, BK=32, cp.async dbl-buf.
// MMA issue is TERM-MAJOR: 16 independent accumulators between RAW reuses.
#define RSB   80u        /* smem bytes per 32-element bf16 row (64B data + 16B pad) */
#define MATSZ 10240u     /* 128 rows * RSB */
#define STAGE (4u * MATSZ)
#define GEMM_SMEM (2 * 4 * 10240)

__device__ __forceinline__ uint32_t s2u(const void* p) {
    uint32_t a;
    asm("{ .reg .u64 t; cvta.to.shared.u64 t, %1; cvt.u32.u64 %0, t; }" : "=r"(a) : "l"(p));
    return a;
}

#define LDSM4(R, addr)                                                              \
    asm volatile("ldmatrix.sync.aligned.m8n8.x4.shared.b16 {%0,%1,%2,%3}, [%4];"    \
                 : "=r"((R)[0]), "=r"((R)[1]), "=r"((R)[2]), "=r"((R)[3])           \
                 : "r"(addr))

__device__ __forceinline__ void mma16816(float* d, const uint32_t* a, const uint32_t* b) {
    asm volatile(
        "mma.sync.aligned.m16n8k16.row.col.f32.bf16.bf16.f32 "
        "{%0,%1,%2,%3}, {%4,%5,%6,%7}, {%8,%9}, {%0,%1,%2,%3};"
        : "+f"(d[0]), "+f"(d[1]), "+f"(d[2]), "+f"(d[3])
        : "r"(a[0]), "r"(a[1]), "r"(a[2]), "r"(a[3]), "r"(b[0]), "r"(b[1]));
}

__global__ __launch_bounds__(256, 1) void gemm_mma_kernel() {
    extern __shared__ char smem[];
    uint32_t sb = s2u(smem);
    int t = threadIdx.x, lane = t & 31, wid = t >> 5;
    int bx = blockIdx.x, by = blockIdx.y;
    int warpM = wid >> 2, warpN = wid & 3;

    const char* gb[4] = {
        (const char*)(g_Ah + (size_t)(by * 128) * KDIM),
        (const char*)(g_Al + (size_t)(by * 128) * KDIM),
        (const char*)(g_Bh + (size_t)(bx * 128) * KDIM),
        (const char*)(g_Bl + (size_t)(bx * 128) * KDIM)
    };

    // per-thread load slots: 2048 16B transfers per stage / 256 threads = 8
    int mats[8], lr[8], lo[8];
    #pragma unroll
    for (int i = 0; i < 8; i++) {
        int idx = i * 256 + t;
        mats[i] = idx >> 9;
        int rem = idx & 511;
        lr[i] = rem >> 2;
        lo[i] = rem & 3;
    }

    float acc[4][4][4];
    #pragma unroll
    for (int a = 0; a < 4; a++)
        #pragma unroll
        for (int b = 0; b < 4; b++)
            #pragma unroll
            for (int c = 0; c < 4; c++) acc[a][b][c] = 0.f;

    const uint32_t aoff = (uint32_t)(warpM * 64 + (lane & 15)) * RSB;
    const uint32_t boff = (uint32_t)(warpN * 32 + (lane & 15)) * RSB;
    const uint32_t khalf = (lane & 16) ? 16u : 0u;  // byte offset of k-half

    // ---- issue stage 0 ----
    #pragma unroll
    for (int i = 0; i < 8; i++) {
        const char* g = gb[mats[i]] + (size_t)lr[i] * 2048 + lo[i] * 16;
        uint32_t s = sb + mats[i] * MATSZ + lr[i] * RSB + lo[i] * 16;
        asm volatile("cp.async.cg.shared.global [%0], [%1], 16;" :: "r"(s), "l"(g));
    }
    asm volatile("cp.async.commit_group;" ::: "memory");

    for (int c = 0; c < 32; c++) {
        if (c < 31) {
            uint32_t bs = sb + ((c + 1) & 1) * STAGE;
            int ko = (c + 1) * 64;
            #pragma unroll
            for (int i = 0; i < 8; i++) {
                const char* g = gb[mats[i]] + (size_t)lr[i] * 2048 + ko + lo[i] * 16;
                uint32_t s = bs + mats[i] * MATSZ + lr[i] * RSB + lo[i] * 16;
                asm volatile("cp.async.cg.shared.global [%0], [%1], 16;" :: "r"(s), "l"(g));
            }
            asm volatile("cp.async.commit_group;" ::: "memory");
            asm volatile("cp.async.wait_group 1;" ::: "memory");
        } else {
            asm volatile("cp.async.wait_group 0;" ::: "memory");
        }
        __syncthreads();

        uint32_t base = sb + (c & 1) * STAGE;
        #pragma unroll
        for (int kc = 0; kc < 2; kc++) {
            uint32_t kb = kc * 32 + khalf;
            uint32_t ah[4][4], al[4][4], bh[4][2], bl[4][2];
            #pragma unroll
            for (int mt = 0; mt < 4; mt++) {
                LDSM4(ah[mt], base + 0 * MATSZ + aoff + mt * 16 * RSB + kb);
                LDSM4(al[mt], base + 1 * MATSZ + aoff + mt * 16 * RSB + kb);
            }
            #pragma unroll
            for (int np = 0; np < 2; np++) {
                uint32_t r[4];
                LDSM4(r, base + 2 * MATSZ + boff + np * 16 * RSB + kb);
                bh[np * 2][0] = r[0]; bh[np * 2][1] = r[2];
                bh[np * 2 + 1][0] = r[1]; bh[np * 2 + 1][1] = r[3];
                LDSM4(r, base + 3 * MATSZ + boff + np * 16 * RSB + kb);
                bl[np * 2][0] = r[0]; bl[np * 2][1] = r[2];
                bl[np * 2 + 1][0] = r[1]; bl[np * 2 + 1][1] = r[3];
            }
            // term-major: 16 independent accs between reuses of the same acc
            #pragma unroll
            for (int mt = 0; mt < 4; mt++)
                #pragma unroll
                for (int nt = 0; nt < 4; nt++)
                    mma16816(acc[mt][nt], ah[mt], bh[nt]);
            #pragma unroll
            for (int mt = 0; mt < 4; mt++)
                #pragma unroll
                for (int nt = 0; nt < 4; nt++)
                    mma16816(acc[mt][nt], ah[mt], bl[nt]);
            #pragma unroll
            for (int mt = 0; mt < 4; mt++)
                #pragma unroll
                for (int nt = 0; nt < 4; nt++)
                    mma16816(acc[mt][nt], al[mt], bh[nt]);
        }
        __syncthreads();
    }

    // ---- epilogue: write C + fused stats ----
    unsigned* smax = (unsigned*)smem;           // 128 entries
    float* sred = (float*)(smem + 512);
    if (t < 128) smax[t] = 0u;
    __syncthreads();

    float lsum = 0.f, lsq = 0.f;
    int q = lane >> 2, pr = (lane & 3) * 2;
    #pragma unroll
    for (int mt = 0; mt < 4; mt++) {
        float rm0 = -3.4e38f, rm1 = -3.4e38f;
        int lrow0 = warpM * 64 + mt * 16 + q;
        int gr0 = by * 128 + lrow0;
        #pragma unroll
        for (int nt = 0; nt < 4; nt++) {
            float c0 = acc[mt][nt][0], c1 = acc[mt][nt][1];
            float c2 = acc[mt][nt][2], c3 = acc[mt][nt][3];
            int col = bx * 128 + warpN * 32 + nt * 8 + pr;
            float2 w0 = { c0, c1 }, w1 = { c2, c3 };
            *(float2*)&g_C[(size_t)gr0 * NROW + col] = w0;
            *(float2*)&g_C[(size_t)(gr0 + 8) * NROW + col] = w1;
            lsum += (c0 + c1) + (c2 + c3);
            lsq += c0 * c0 + c1 * c1 + c2 * c2 + c3 * c3;
            rm0 = fmaxf(rm0, fmaxf(c0, c1));
            rm1 = fmaxf(rm1, fmaxf(c2, c3));
        }
        atomicMax(&smax[lrow0], fmap(rm0));
        atomicMax(&smax[lrow0 + 8], fmap(rm1));
    }

    #pragma unroll
    for (int o = 16; o; o >>= 1) {
        lsum += __shfl_down_sync(0xffffffffu, lsum, o);
        lsq  += __shfl_down_sync(0xffffffffu, lsq,  o);
    }
    if (lane == 0) { sred[wid] = lsum; sred[8 + wid] = lsq; }
    __syncthreads();
    if (t == 0) {
        float s0 = 0.f, s1 = 0.f;
        #pragma unroll
        for (int w = 0; w < 8; w++) { s0 += sred[w]; s1 += sred[8 + w]; }
        atomicAdd(&g_sum, (double)s0);
        atomicAdd(&g_sumsq, (double)s1);
    }
    if (t < 128) atomicMax(&g_rowmax_u[by * 128 + t], smax[t]);
}

// ---------------- stats: mean / invstd (ddof=1) ---------------------------------
__global__ void stats_kernel() {
    double n = NTOTD;
    double mean = g_sum / n;
    double var = (g_sumsq - g_sum * g_sum / n) / (n - 1.0);
    g_mean = (float)mean;
    g_invstd = (float)(1.0 / sqrt(var));
}

__global__ void rowmaxM_kernel() {
    int i = blockIdx.x * 256 + threadIdx.x;
    g_rowmaxM[i] = (funmap(g_rowmax_u[i]) - g_mean) * g_invstd;
}

// ---------------- standardize M (g_C aligned + outM scalar) + build bf16 P0 -----
__global__ void transform_kernel(float* __restrict__ outM) {
    unsigned idx = blockIdx.x * 256 + threadIdx.x;  // float4 index, 4194304 total
    unsigned row = idx >> 10;
    float4 c = ((const float4*)g_C)[idx];
    float mean = g_mean, is = g_invstd, rm = g_rowmaxM[row];
    float m0 = (c.x - mean) * is;
    float m1 = (c.y - mean) * is;
    float m2 = (c.z - mean) * is;
    float m3 = (c.w - mean) * is;
    float4 mm = { m0, m1, m2, m3 };
    ((float4*)g_C)[idx] = mm;
    // outM is only 4-byte aligned (out + 1 + N*N) -> scalar stores ONLY
    unsigned o = idx * 4;
    outM[o + 0] = m0; outM[o + 1] = m1; outM[o + 2] = m2; outM[o + 3] = m3;
    __nv_bfloat162 h0, h1;
    h0.x = __float2bfloat16_rn(expf(m0 - rm));
    h0.y = __float2bfloat16_rn(expf(m1 - rm));
    h1.x = __float2bfloat16_rn(expf(m2 - rm));
    h1.y = __float2bfloat16_rn(expf(m3 - rm));
    ((__nv_bfloat162*)g_P0)[idx * 2]     = h0;
    ((__nv_bfloat162*)g_P0)[idx * 2 + 1] = h1;
}

// ---------------- Sinkhorn iteration kernels ------------------------------------
#define RC_CONST 2.44140625e-4f  /* 1/4096 */

__global__ void sinkA_kernel() {  // S_i = sum_j P0[i][j]*v[j];  u_i = r/S_i
    if (g_done) return;
    int row = blockIdx.x;
    const uint4* p = (const uint4*)(g_P0 + (size_t)row * NROW);
    const float4* v4 = (const float4*)g_v;
    float acc = 0.f;
    #pragma unroll
    for (int c = 0; c < 4; c++) {
        int idx = threadIdx.x + 128 * c;
        uint4 q = p[idx];
        float4 va = v4[idx * 2], vb = v4[idx * 2 + 1];
        float2 f0 = __bfloat1622float2(*reinterpret_cast<__nv_bfloat162*>(&q.x));
        float2 f1 = __bfloat1622float2(*reinterpret_cast<__nv_bfloat162*>(&q.y));
        float2 f2 = __bfloat1622float2(*reinterpret_cast<__nv_bfloat162*>(&q.z));
        float2 f3 = __bfloat1622float2(*reinterpret_cast<__nv_bfloat162*>(&q.w));
        acc += f0.x * va.x + f0.y * va.y + f1.x * va.z + f1.y * va.w;
        acc += f2.x * vb.x + f2.y * vb.y + f3.x * vb.z + f3.y * vb.w;
    }
    acc = blockReduceSum128(acc);
    if (threadIdx.x == 0) g_u[row] = RC_CONST / acc;
}

// sinkB: column pass + last-block-done finalize (absorbs old sinkD kernel)
__global__ void sinkB_kernel() {
    __shared__ unsigned ticket;
    __shared__ float smax[8];
    __shared__ int sflag;
    if (g_done) return;
    int t = threadIdx.x;
    int col = blockIdx.x * 256 + t;
    int i0 = blockIdx.y * 128;
    const __nv_bfloat16* p = g_P0 + (size_t)i0 * NROW + col;
    float acc = 0.f;
    #pragma unroll 4
    for (int i = 0; i < 128; i++)
        acc += __bfloat162float(p[(size_t)i * NROW]) * g_u[i0 + i];
    atomicAdd(&g_T[col], acc);
    __threadfence();
    if (t == 0) ticket = atomicAdd(&g_ctr, 1u);
    __syncthreads();
    if (ticket != 511u) return;   // not the last block

    // ---- finalize (runs in exactly one block, after all T contributions) ----
    float tv[16], dev = 0.f;
    #pragma unroll
    for (int q = 0; q < 16; q++) {
        int j = t + 256 * q;
        tv[q] = g_T[j];
        dev = fmaxf(dev, fabsf(g_v[j] * tv[q] - RC_CONST));
    }
    #pragma unroll
    for (int o = 16; o; o >>= 1) dev = fmaxf(dev, __shfl_down_sync(0xffffffffu, dev, o));
    if ((t & 31) == 0) smax[t >> 5] = dev;
    __syncthreads();
    if (t == 0) {
        float m = 0.f;
        #pragma unroll
        for (int w = 0; w < 8; w++) m = fmaxf(m, smax[w]);
        sflag = (m <= 1e-6f) ? 1 : 0;
        if (sflag) g_done = 1;
        g_ctr = 0u;               // reset ticket for next iteration / replay
    }
    __syncthreads();
    #pragma unroll
    for (int q = 0; q < 16; q++) {
        int j = t + 256 * q;
        if (!sflag) g_v[j] = RC_CONST / tv[q];
        g_T[j] = 0.f;
    }
}

// ---------------- final renormalization (fp32 P0 recomputed from g_C) -----------
__global__ void f1_kernel() {  // af_i = 1 / sum_j exp(M_ij - rmax_i)*v_j
    int row = blockIdx.x;
    const float4* m4 = (const float4*)(g_C + (size_t)row * NROW);
    const float4* v4 = (const float4*)g_v;
    float rm = g_rowmaxM[row], acc = 0.f;
    #pragma unroll
    for (int c = 0; c < 8; c++) {
        int idx = threadIdx.x + 128 * c;
        float4 m = m4[idx];
        float4 v = v4[idx];
        acc += expf(m.x - rm) * v.x + expf(m.y - rm) * v.y
             + expf(m.z - rm) * v.z + expf(m.w - rm) * v.w;
    }
    acc = blockReduceSum128(acc);
    if (threadIdx.x == 0) g_af[row] = 1.0f / acc;
}

// f2: column pass + last-block inversion of Tf (absorbs old f2b kernel)
__global__ void f2_kernel() {
    __shared__ unsigned ticket;
    int t = threadIdx.x;
    int col = blockIdx.x * 256 + t;
    int i0 = blockIdx.y * 128;
    const float* p = g_C + (size_t)i0 * NROW + col;
    float acc = 0.f;
    #pragma unroll 4
    for (int i = 0; i < 128; i++)
        acc += expf(p[(size_t)i * NROW] - g_rowmaxM[i0 + i]) * g_af[i0 + i];
    atomicAdd(&g_Tf[col], acc);
    __threadfence();
    if (t == 0) ticket = atomicAdd(&g_ctr, 1u);
    __syncthreads();
    if (ticket != 511u) return;
    #pragma unroll
    for (int q = 0; q < 16; q++) {
        int j = t + 256 * q;
        g_Tf[j] = 1.0f / g_Tf[j];
    }
    if (t == 0) g_ctr = 0u;
}

__global__ void f3_kernel(float* __restrict__ outP) {  // P + loss accumulation
    int row = blockIdx.x;
    float rm = g_rowmaxM[row], a = g_af[row];
    const float4* m4 = (const float4*)(g_C + (size_t)row * NROW);
    float* op = outP + (size_t)row * NROW;   // 4B-aligned only: scalar stores
    float lacc = 0.f;
    #pragma unroll
    for (int c = 0; c < 8; c++) {
        int idx = threadIdx.x + 128 * c;
        float4 m = m4[idx];
        int j0 = idx * 4;
        float p0 = expf(m.x - rm) * a * g_Tf[j0 + 0];
        float p1 = expf(m.y - rm) * a * g_Tf[j0 + 1];
        float p2 = expf(m.z - rm) * a * g_Tf[j0 + 2];
        float p3 = expf(m.w - rm) * a * g_Tf[j0 + 3];
        op[j0 + 0] = p0; op[j0 + 1] = p1; op[j0 + 2] = p2; op[j0 + 3] = p3;
        float d0 = p0 - ((j0 + 0) == row ? 1.0f : 0.0f);
        float d1 = p1 - ((j0 + 1) == row ? 1.0f : 0.0f);
        float d2 = p2 - ((j0 + 2) == row ? 1.0f : 0.0f);
        float d3 = p3 - ((j0 + 3) == row ? 1.0f : 0.0f);
        lacc += d0 * d0 + d1 * d1 + d2 * d2 + d3 * d3;
    }
    lacc = blockReduceSum128(lacc);
    if (threadIdx.x == 0) atomicAdd(&g_loss, (double)lacc);
}

__global__ void f4_kernel(float* __restrict__ out) {
    out[0] = (float)sqrt(g_loss);
}

// ---------------- launch --------------------------------------------------------
extern "C" void kernel_launch(void* const* d_in, const int* in_sizes, int n_in,
                              void* d_out, int out_size) {
    const float* ft = (const float*)d_in[0];
    const float* fs = (const float*)d_in[1];
    float* out = (float*)d_out;
    float* outP = out + 1;
    float* outM = out + 1 + (size_t)NROW * NROW;

    cudaFuncSetAttribute(gemm_mma_kernel, cudaFuncAttributeMaxDynamicSharedMemorySize,
                         GEMM_SMEM);

    init_kernel<<<16, 256>>>();
    rownorm_kernel<<<2 * NROW, 128>>>(ft, fs);
    split_kernel<<<8192, 256>>>(ft, fs);
    gemm_mma_kernel<<<dim3(32, 32), 256, GEMM_SMEM>>>();
    stats_kernel<<<1, 1>>>();
    rowmaxM_kernel<<<16, 256>>>();
    transform_kernel<<<16384, 256>>>(outM);

    for (int it = 0; it < 20; ++it) {
        sinkA_kernel<<<NROW, 128>>>();
        sinkB_kernel<<<dim3(16, 32), 256>>>();
    }

    f1_kernel<<<NROW, 128>>>();
    f2_kernel<<<dim3(16, 32), 256>>>();
    f3_kernel<<<NROW, 128>>>(outP);
    f4_kernel<<<1, 1>>>(out);
}

// round 15
// speedup vs baseline: 2.2747x; 1.2069x over previous
#include <cuda_runtime.h>
#include <cuda_fp16.h>
#include <cuda_bf16.h>
#include <cstdint>

#define NROW 4096
#define KDIM 1024
#define NTOTD 16777216.0

// ---------------- static device scratch (no allocations allowed) ----------------
static __device__ float          g_C[(size_t)NROW * NROW];      // 64 MB: raw C then standardized M
static __device__ __nv_bfloat16  g_P0[(size_t)NROW * NROW];     // 32 MB: exp(M - rowmax) in bf16
static __device__ __half         g_Ah[(size_t)NROW * KDIM];     // prescaled ft hi (fp16)
static __device__ __half         g_Al[(size_t)NROW * KDIM];     // prescaled ft lo (fp16)
static __device__ __half         g_Bh[(size_t)NROW * KDIM];     // prescaled fs hi (fp16)
static __device__ float          g_invn[2 * NROW];              // inverse row norms (ft then fs)
static __device__ unsigned       g_rowmax_u[NROW];              // order-mapped float for atomicMax
static __device__ float          g_rowmaxM[NROW];
static __device__ float          g_u[NROW], g_v[NROW], g_T[NROW], g_af[NROW], g_Tf[NROW];
static __device__ double         g_sum, g_sumsq, g_loss;
static __device__ float          g_mean, g_invstd;
static __device__ int            g_done;
static __device__ unsigned       g_ctr;                         // last-block ticket counter

__device__ __forceinline__ unsigned fmap(float f) {
    unsigned u = __float_as_uint(f);
    return (u & 0x80000000u) ? ~u : (u | 0x80000000u);
}
__device__ __forceinline__ float funmap(unsigned s) {
    unsigned b = (s & 0x80000000u) ? (s ^ 0x80000000u) : ~s;
    return __uint_as_float(b);
}

__device__ __forceinline__ float blockReduceSum128(float v) {
    __shared__ float s[4];
    #pragma unroll
    for (int o = 16; o; o >>= 1) v += __shfl_down_sync(0xffffffffu, v, o);
    if ((threadIdx.x & 31) == 0) s[threadIdx.x >> 5] = v;
    __syncthreads();
    if (threadIdx.x == 0) v = s[0] + s[1] + s[2] + s[3];
    return v;  // valid on thread 0 only
}

// ---------------- init: reset all persistent state (graph replays!) -------------
__global__ void init_kernel() {
    int i = blockIdx.x * 256 + threadIdx.x;  // 4096 threads
    g_v[i] = 1.0f;
    g_T[i] = 0.0f;
    g_Tf[i] = 0.0f;
    g_rowmax_u[i] = 0u;
    if (i == 0) { g_done = 0; g_sum = 0.0; g_sumsq = 0.0; g_loss = 0.0; g_ctr = 0u; }
}

// ---------------- row norms of ft / fs ------------------------------------------
__global__ void rownorm_kernel(const float* __restrict__ ft, const float* __restrict__ fs) {
    int row = blockIdx.x;  // 0..8191
    const float* src = (row < NROW) ? ft + (size_t)row * KDIM
                                    : fs + (size_t)(row - NROW) * KDIM;
    const float4* s4 = (const float4*)src;
    float acc = 0.f;
    #pragma unroll
    for (int c = 0; c < 2; c++) {
        float4 v = s4[threadIdx.x + 128 * c];
        acc += v.x * v.x + v.y * v.y + v.z * v.z + v.w * v.w;
    }
    acc = blockReduceSum128(acc);
    if (threadIdx.x == 0) g_invn[row] = 1.0f / fmaxf(sqrtf(acc), 1e-12f);
}

// ---------------- split: prescale by invn, fp16 hi/lo (A) / hi-only (B) ---------
__global__ void split_kernel(const float* __restrict__ ft, const float* __restrict__ fs) {
    int i = blockIdx.x * 256 + threadIdx.x;   // float4 index, 2*4096*256 total
    int row = i >> 8;                         // 0..8191
    float sc = g_invn[row];
    float4 v;
    if (row < NROW) v = ((const float4*)ft)[i];
    else            v = ((const float4*)fs)[i - NROW * 256];
    v.x *= sc; v.y *= sc; v.z *= sc; v.w *= sc;
    __half h0 = __float2half_rn(v.x);
    __half h1 = __float2half_rn(v.y);
    __half h2 = __float2half_rn(v.z);
    __half h3 = __float2half_rn(v.w);
    __half2 hp0 = { h0, h1 }, hp1 = { h2, h3 };
    if (row < NROW) {
        __half l0 = __float2half_rn(v.x - __half2float(h0));
        __half l1 = __float2half_rn(v.y - __half2float(h1));
        __half l2 = __float2half_rn(v.z - __half2float(h2));
        __half l3 = __float2half_rn(v.w - __half2float(h3));
        __half2 lp0 = { l0, l1 }, lp1 = { l2, l3 };
        ((__half2*)g_Ah)[i * 2] = hp0; ((__half2*)g_Ah)[i * 2 + 1] = hp1;
        ((__half2*)g_Al)[i * 2] = lp0; ((__half2*)g_Al)[i * 2 + 1] = lp1;
    } else {
        int j = i - NROW * 256;
        ((__half2*)g_Bh)[j * 2] = hp0; ((__half2*)g_Bh)[j * 2 + 1] = hp1;
    }
}

// ---------------- mma.sync fp16 2-term GEMM + fused stats -----------------------
// C[i][j] = Ah_i.Bh_j + Al_i.Bh_j   (A = Ah+Al reconstructs fp32 to ~2^-22;
//                                    dropped A.Bl term ~2.8e-4 on standardized M)
// CTA tile 128x128, 8 warps (2 M x 4 N), warp tile 64x32, BK=32, cp.async dbl-buf.
#define RSB   80u        /* smem bytes per 32-element fp16 row (64B data + 16B pad) */
#define MATSZ 10240u     /* 128 rows * RSB */
#define STAGE (3u * MATSZ)
#define GEMM_SMEM (2 * 3 * 10240)

__device__ __forceinline__ uint32_t s2u(const void* p) {
    uint32_t a;
    asm("{ .reg .u64 t; cvta.to.shared.u64 t, %1; cvt.u32.u64 %0, t; }" : "=r"(a) : "l"(p));
    return a;
}

#define LDSM4(R, addr)                                                              \
    asm volatile("ldmatrix.sync.aligned.m8n8.x4.shared.b16 {%0,%1,%2,%3}, [%4];"    \
                 : "=r"((R)[0]), "=r"((R)[1]), "=r"((R)[2]), "=r"((R)[3])           \
                 : "r"(addr))

__device__ __forceinline__ void mma16816(float* d, const uint32_t* a, const uint32_t* b) {
    asm volatile(
        "mma.sync.aligned.m16n8k16.row.col.f32.f16.f16.f32 "
        "{%0,%1,%2,%3}, {%4,%5,%6,%7}, {%8,%9}, {%0,%1,%2,%3};"
        : "+f"(d[0]), "+f"(d[1]), "+f"(d[2]), "+f"(d[3])
        : "r"(a[0]), "r"(a[1]), "r"(a[2]), "r"(a[3]), "r"(b[0]), "r"(b[1]));
}

__global__ __launch_bounds__(256, 1) void gemm_mma_kernel() {
    extern __shared__ char smem[];
    uint32_t sb = s2u(smem);
    int t = threadIdx.x, lane = t & 31, wid = t >> 5;
    int bx = blockIdx.x, by = blockIdx.y;
    int warpM = wid >> 2, warpN = wid & 3;

    const char* gb[3] = {
        (const char*)(g_Ah + (size_t)(by * 128) * KDIM),
        (const char*)(g_Al + (size_t)(by * 128) * KDIM),
        (const char*)(g_Bh + (size_t)(bx * 128) * KDIM)
    };

    // per-thread load slots: 1536 16B transfers per stage / 256 threads = 6
    int mats[6], lr[6], lo[6];
    #pragma unroll
    for (int i = 0; i < 6; i++) {
        int idx = i * 256 + t;
        mats[i] = idx >> 9;
        int rem = idx & 511;
        lr[i] = rem >> 2;
        lo[i] = rem & 3;
    }

    float acc[4][4][4];
    #pragma unroll
    for (int a = 0; a < 4; a++)
        #pragma unroll
        for (int b = 0; b < 4; b++)
            #pragma unroll
            for (int c = 0; c < 4; c++) acc[a][b][c] = 0.f;

    const uint32_t aoff = (uint32_t)(warpM * 64 + (lane & 15)) * RSB;
    const uint32_t boff = (uint32_t)(warpN * 32 + (lane & 15)) * RSB;
    const uint32_t khalf = (lane & 16) ? 16u : 0u;  // byte offset of k-half

    // ---- issue stage 0 ----
    #pragma unroll
    for (int i = 0; i < 6; i++) {
        const char* g = gb[mats[i]] + (size_t)lr[i] * 2048 + lo[i] * 16;
        uint32_t s = sb + mats[i] * MATSZ + lr[i] * RSB + lo[i] * 16;
        asm volatile("cp.async.cg.shared.global [%0], [%1], 16;" :: "r"(s), "l"(g));
    }
    asm volatile("cp.async.commit_group;" ::: "memory");

    for (int c = 0; c < 32; c++) {
        if (c < 31) {
            uint32_t bs = sb + ((c + 1) & 1) * STAGE;
            int ko = (c + 1) * 64;
            #pragma unroll
            for (int i = 0; i < 6; i++) {
                const char* g = gb[mats[i]] + (size_t)lr[i] * 2048 + ko + lo[i] * 16;
                uint32_t s = bs + mats[i] * MATSZ + lr[i] * RSB + lo[i] * 16;
                asm volatile("cp.async.cg.shared.global [%0], [%1], 16;" :: "r"(s), "l"(g));
            }
            asm volatile("cp.async.commit_group;" ::: "memory");
            asm volatile("cp.async.wait_group 1;" ::: "memory");
        } else {
            asm volatile("cp.async.wait_group 0;" ::: "memory");
        }
        __syncthreads();

        uint32_t base = sb + (c & 1) * STAGE;
        #pragma unroll
        for (int kc = 0; kc < 2; kc++) {
            uint32_t kb = kc * 32 + khalf;
            uint32_t ah[4][4], al[4][4], bh[4][2];
            #pragma unroll
            for (int mt = 0; mt < 4; mt++) {
                LDSM4(ah[mt], base + 0 * MATSZ + aoff + mt * 16 * RSB + kb);
                LDSM4(al[mt], base + 1 * MATSZ + aoff + mt * 16 * RSB + kb);
            }
            #pragma unroll
            for (int np = 0; np < 2; np++) {
                uint32_t r[4];
                LDSM4(r, base + 2 * MATSZ + boff + np * 16 * RSB + kb);
                bh[np * 2][0] = r[0]; bh[np * 2][1] = r[2];
                bh[np * 2 + 1][0] = r[1]; bh[np * 2 + 1][1] = r[3];
            }
            #pragma unroll
            for (int mt = 0; mt < 4; mt++)
                #pragma unroll
                for (int nt = 0; nt < 4; nt++)
                    mma16816(acc[mt][nt], ah[mt], bh[nt]);
            #pragma unroll
            for (int mt = 0; mt < 4; mt++)
                #pragma unroll
                for (int nt = 0; nt < 4; nt++)
                    mma16816(acc[mt][nt], al[mt], bh[nt]);
        }
        __syncthreads();
    }

    // ---- epilogue: write C + fused stats ----
    unsigned* smax = (unsigned*)smem;           // 128 entries
    float* sred = (float*)(smem + 512);
    if (t < 128) smax[t] = 0u;
    __syncthreads();

    float lsum = 0.f, lsq = 0.f;
    int q = lane >> 2, pr = (lane & 3) * 2;
    #pragma unroll
    for (int mt = 0; mt < 4; mt++) {
        float rm0 = -3.4e38f, rm1 = -3.4e38f;
        int lrow0 = warpM * 64 + mt * 16 + q;
        int gr0 = by * 128 + lrow0;
        #pragma unroll
        for (int nt = 0; nt < 4; nt++) {
            float c0 = acc[mt][nt][0], c1 = acc[mt][nt][1];
            float c2 = acc[mt][nt][2], c3 = acc[mt][nt][3];
            int col = bx * 128 + warpN * 32 + nt * 8 + pr;
            float2 w0 = { c0, c1 }, w1 = { c2, c3 };
            *(float2*)&g_C[(size_t)gr0 * NROW + col] = w0;
            *(float2*)&g_C[(size_t)(gr0 + 8) * NROW + col] = w1;
            lsum += (c0 + c1) + (c2 + c3);
            lsq += c0 * c0 + c1 * c1 + c2 * c2 + c3 * c3;
            rm0 = fmaxf(rm0, fmaxf(c0, c1));
            rm1 = fmaxf(rm1, fmaxf(c2, c3));
        }
        atomicMax(&smax[lrow0], fmap(rm0));
        atomicMax(&smax[lrow0 + 8], fmap(rm1));
    }

    #pragma unroll
    for (int o = 16; o; o >>= 1) {
        lsum += __shfl_down_sync(0xffffffffu, lsum, o);
        lsq  += __shfl_down_sync(0xffffffffu, lsq,  o);
    }
    if (lane == 0) { sred[wid] = lsum; sred[8 + wid] = lsq; }
    __syncthreads();
    if (t == 0) {
        float s0 = 0.f, s1 = 0.f;
        #pragma unroll
        for (int w = 0; w < 8; w++) { s0 += sred[w]; s1 += sred[8 + w]; }
        atomicAdd(&g_sum, (double)s0);
        atomicAdd(&g_sumsq, (double)s1);
    }
    if (t < 128) atomicMax(&g_rowmax_u[by * 128 + t], smax[t]);
}

// ---------------- stats: mean / invstd (ddof=1) ---------------------------------
__global__ void stats_kernel() {
    double n = NTOTD;
    double mean = g_sum / n;
    double var = (g_sumsq - g_sum * g_sum / n) / (n - 1.0);
    g_mean = (float)mean;
    g_invstd = (float)(1.0 / sqrt(var));
}

__global__ void rowmaxM_kernel() {
    int i = blockIdx.x * 256 + threadIdx.x;
    g_rowmaxM[i] = (funmap(g_rowmax_u[i]) - g_mean) * g_invstd;
}

// ---------------- standardize M (g_C aligned + outM scalar) + build bf16 P0 -----
__global__ void transform_kernel(float* __restrict__ outM) {
    unsigned idx = blockIdx.x * 256 + threadIdx.x;  // float4 index, 4194304 total
    unsigned row = idx >> 10;
    float4 c = ((const float4*)g_C)[idx];
    float mean = g_mean, is = g_invstd, rm = g_rowmaxM[row];
    float m0 = (c.x - mean) * is;
    float m1 = (c.y - mean) * is;
    float m2 = (c.z - mean) * is;
    float m3 = (c.w - mean) * is;
    float4 mm = { m0, m1, m2, m3 };
    ((float4*)g_C)[idx] = mm;
    // outM is only 4-byte aligned (out + 1 + N*N) -> scalar stores ONLY
    unsigned o = idx * 4;
    outM[o + 0] = m0; outM[o + 1] = m1; outM[o + 2] = m2; outM[o + 3] = m3;
    __nv_bfloat162 h0, h1;
    h0.x = __float2bfloat16_rn(expf(m0 - rm));
    h0.y = __float2bfloat16_rn(expf(m1 - rm));
    h1.x = __float2bfloat16_rn(expf(m2 - rm));
    h1.y = __float2bfloat16_rn(expf(m3 - rm));
    ((__nv_bfloat162*)g_P0)[idx * 2]     = h0;
    ((__nv_bfloat162*)g_P0)[idx * 2 + 1] = h1;
}

// ---------------- Sinkhorn iteration kernels ------------------------------------
#define RC_CONST 2.44140625e-4f  /* 1/4096 */

__global__ void sinkA_kernel() {  // S_i = sum_j P0[i][j]*v[j];  u_i = r/S_i
    if (g_done) return;
    int row = blockIdx.x;
    const uint4* p = (const uint4*)(g_P0 + (size_t)row * NROW);
    const float4* v4 = (const float4*)g_v;
    float acc = 0.f;
    #pragma unroll
    for (int c = 0; c < 4; c++) {
        int idx = threadIdx.x + 128 * c;
        uint4 q = p[idx];
        float4 va = v4[idx * 2], vb = v4[idx * 2 + 1];
        float2 f0 = __bfloat1622float2(*reinterpret_cast<__nv_bfloat162*>(&q.x));
        float2 f1 = __bfloat1622float2(*reinterpret_cast<__nv_bfloat162*>(&q.y));
        float2 f2 = __bfloat1622float2(*reinterpret_cast<__nv_bfloat162*>(&q.z));
        float2 f3 = __bfloat1622float2(*reinterpret_cast<__nv_bfloat162*>(&q.w));
        acc += f0.x * va.x + f0.y * va.y + f1.x * va.z + f1.y * va.w;
        acc += f2.x * vb.x + f2.y * vb.y + f3.x * vb.z + f3.y * vb.w;
    }
    acc = blockReduceSum128(acc);
    if (threadIdx.x == 0) g_u[row] = RC_CONST / acc;
}

// sinkB: column pass + last-block-done finalize (absorbs old sinkD kernel)
__global__ void sinkB_kernel() {
    __shared__ unsigned ticket;
    __shared__ float smax[8];
    __shared__ int sflag;
    if (g_done) return;
    int t = threadIdx.x;
    int col = blockIdx.x * 256 + t;
    int i0 = blockIdx.y * 128;
    const __nv_bfloat16* p = g_P0 + (size_t)i0 * NROW + col;
    float acc = 0.f;
    #pragma unroll 4
    for (int i = 0; i < 128; i++)
        acc += __bfloat162float(p[(size_t)i * NROW]) * g_u[i0 + i];
    atomicAdd(&g_T[col], acc);
    __threadfence();
    if (t == 0) ticket = atomicAdd(&g_ctr, 1u);
    __syncthreads();
    if (ticket != 511u) return;   // not the last block

    // ---- finalize (runs in exactly one block, after all T contributions) ----
    float tv[16], dev = 0.f;
    #pragma unroll
    for (int q = 0; q < 16; q++) {
        int j = t + 256 * q;
        tv[q] = g_T[j];
        dev = fmaxf(dev, fabsf(g_v[j] * tv[q] - RC_CONST));
    }
    #pragma unroll
    for (int o = 16; o; o >>= 1) dev = fmaxf(dev, __shfl_down_sync(0xffffffffu, dev, o));
    if ((t & 31) == 0) smax[t >> 5] = dev;
    __syncthreads();
    if (t == 0) {
        float m = 0.f;
        #pragma unroll
        for (int w = 0; w < 8; w++) m = fmaxf(m, smax[w]);
        sflag = (m <= 1e-6f) ? 1 : 0;
        if (sflag) g_done = 1;
        g_ctr = 0u;               // reset ticket for next iteration / replay
    }
    __syncthreads();
    #pragma unroll
    for (int q = 0; q < 16; q++) {
        int j = t + 256 * q;
        if (!sflag) g_v[j] = RC_CONST / tv[q];
        g_T[j] = 0.f;
    }
}

// ---------------- final renormalization (fp32 P0 recomputed from g_C) -----------
__global__ void f1_kernel() {  // af_i = 1 / sum_j exp(M_ij - rmax_i)*v_j
    int row = blockIdx.x;
    const float4* m4 = (const float4*)(g_C + (size_t)row * NROW);
    const float4* v4 = (const float4*)g_v;
    float rm = g_rowmaxM[row], acc = 0.f;
    #pragma unroll
    for (int c = 0; c < 8; c++) {
        int idx = threadIdx.x + 128 * c;
        float4 m = m4[idx];
        float4 v = v4[idx];
        acc += expf(m.x - rm) * v.x + expf(m.y - rm) * v.y
             + expf(m.z - rm) * v.z + expf(m.w - rm) * v.w;
    }
    acc = blockReduceSum128(acc);
    if (threadIdx.x == 0) g_af[row] = 1.0f / acc;
}

// f2: column pass + last-block inversion of Tf (absorbs old f2b kernel)
__global__ void f2_kernel() {
    __shared__ unsigned ticket;
    int t = threadIdx.x;
    int col = blockIdx.x * 256 + t;
    int i0 = blockIdx.y * 128;
    const float* p = g_C + (size_t)i0 * NROW + col;
    float acc = 0.f;
    #pragma unroll 4
    for (int i = 0; i < 128; i++)
        acc += expf(p[(size_t)i * NROW] - g_rowmaxM[i0 + i]) * g_af[i0 + i];
    atomicAdd(&g_Tf[col], acc);
    __threadfence();
    if (t == 0) ticket = atomicAdd(&g_ctr, 1u);
    __syncthreads();
    if (ticket != 511u) return;
    #pragma unroll
    for (int q = 0; q < 16; q++) {
        int j = t + 256 * q;
        g_Tf[j] = 1.0f / g_Tf[j];
    }
    if (t == 0) g_ctr = 0u;
}

__global__ void f3_kernel(float* __restrict__ outP) {  // P + loss accumulation
    int row = blockIdx.x;
    float rm = g_rowmaxM[row], a = g_af[row];
    const float4* m4 = (const float4*)(g_C + (size_t)row * NROW);
    float* op = outP + (size_t)row * NROW;   // 4B-aligned only: scalar stores
    float lacc = 0.f;
    #pragma unroll
    for (int c = 0; c < 8; c++) {
        int idx = threadIdx.x + 128 * c;
        float4 m = m4[idx];
        int j0 = idx * 4;
        float p0 = expf(m.x - rm) * a * g_Tf[j0 + 0];
        float p1 = expf(m.y - rm) * a * g_Tf[j0 + 1];
        float p2 = expf(m.z - rm) * a * g_Tf[j0 + 2];
        float p3 = expf(m.w - rm) * a * g_Tf[j0 + 3];
        op[j0 + 0] = p0; op[j0 + 1] = p1; op[j0 + 2] = p2; op[j0 + 3] = p3;
        float d0 = p0 - ((j0 + 0) == row ? 1.0f : 0.0f);
        float d1 = p1 - ((j0 + 1) == row ? 1.0f : 0.0f);
        float d2 = p2 - ((j0 + 2) == row ? 1.0f : 0.0f);
        float d3 = p3 - ((j0 + 3) == row ? 1.0f : 0.0f);
        lacc += d0 * d0 + d1 * d1 + d2 * d2 + d3 * d3;
    }
    lacc = blockReduceSum128(lacc);
    if (threadIdx.x == 0) atomicAdd(&g_loss, (double)lacc);
}

__global__ void f4_kernel(float* __restrict__ out) {
    out[0] = (float)sqrt(g_loss);
}

// ---------------- launch --------------------------------------------------------
extern "C" void kernel_launch(void* const* d_in, const int* in_sizes, int n_in,
                              void* d_out, int out_size) {
    const float* ft = (const float*)d_in[0];
    const float* fs = (const float*)d_in[1];
    float* out = (float*)d_out;
    float* outP = out + 1;
    float* outM = out + 1 + (size_t)NROW * NROW;

    cudaFuncSetAttribute(gemm_mma_kernel, cudaFuncAttributeMaxDynamicSharedMemorySize,
                         GEMM_SMEM);

    init_kernel<<<16, 256>>>();
    rownorm_kernel<<<2 * NROW, 128>>>(ft, fs);
    split_kernel<<<8192, 256>>>(ft, fs);
    gemm_mma_kernel<<<dim3(32, 32), 256, GEMM_SMEM>>>();
    stats_kernel<<<1, 1>>>();
    rowmaxM_kernel<<<16, 256>>>();
    transform_kernel<<<16384, 256>>>(outM);

    for (int it = 0; it < 20; ++it) {
        sinkA_kernel<<<NROW, 128>>>();
        sinkB_kernel<<<dim3(16, 32), 256>>>();
    }

    f1_kernel<<<NROW, 128>>>();
    f2_kernel<<<dim3(16, 32), 256>>>();
    f3_kernel<<<NROW, 128>>>(outP);
    f4_kernel<<<1, 1>>>(out);
}